// round 14
// baseline (speedup 1.0000x reference)
#include <cuda_runtime.h>
#include <cuda_fp16.h>
#include <cstdint>

// ---------------- problem constants ----------------
#define NIMG 8
#define NC   32
#define NV   128
#define HH   128
#define WW   128
#define CIN  64
#define CC   65
#define CMID 256
#define HP   130
#define KREAL 585          // 65 * 9, k = ci*9 + ky*3 + kx
#define KPAD  640
#define CHUNK 64
#define NCH   10

// shifted-input buffer strides (fp16 elements); rows are 128 wide, 130 tall
#define CS  (HP * 128)           // per channel  = 16640
#define NS  (CC * CS)            // per image    = 1081600
#define KXS (NIMG * NS)          // per kx shift = 8652800

// ---------------- device scratch ----------------
__device__ float    g_Fx[NC * NV * WW];
__device__ float    g_Fy[NC * NV * HH];
__device__ uint16_t g_Xs[3 * KXS];       // 3 kx-shifted fp16 padded inputs (52MB)
__device__ uint4    g_wBh4[NCH * 2048];  // pre-swizzled fp16 weight planes
__device__ int      g_batch[NC];

// ---------------- helpers ----------------
__device__ __forceinline__ uint32_t smem_u32(const void* p) {
    uint32_t a;
    asm("{ .reg .u64 t; cvta.to.shared.u64 t, %1; cvt.u32.u64 %0, t; }"
        : "=r"(a) : "l"(p));
    return a;
}
__device__ __forceinline__ void ldm_x4_trans(uint32_t* r, uint32_t a) {
    asm volatile("ldmatrix.sync.aligned.m8n8.x4.trans.shared.b16 {%0,%1,%2,%3}, [%4];"
        : "=r"(r[0]), "=r"(r[1]), "=r"(r[2]), "=r"(r[3]) : "r"(a));
}
__device__ __forceinline__ void ldm_x2(uint32_t* r, uint32_t a) {
    asm volatile("ldmatrix.sync.aligned.m8n8.x2.shared.b16 {%0,%1}, [%2];"
        : "=r"(r[0]), "=r"(r[1]) : "r"(a));
}
__device__ __forceinline__ void mma_fp16(float* d, const uint32_t* a, const uint32_t* b) {
    asm volatile("mma.sync.aligned.m16n8k16.row.col.f32.f16.f16.f32 "
        "{%0,%1,%2,%3}, {%4,%5,%6,%7}, {%8,%9}, {%0,%1,%2,%3};"
        : "+f"(d[0]), "+f"(d[1]), "+f"(d[2]), "+f"(d[3])
        : "r"(a[0]), "r"(a[1]), "r"(a[2]), "r"(a[3]), "r"(b[0]), "r"(b[1]));
}
#define CP_ASYNC16(dst, src) \
    asm volatile("cp.async.cg.shared.global [%0], [%1], 16;" \
                 :: "r"(dst), "l"(src) : "memory")
#define CP_ASYNC16Z(dst, src, sz) \
    asm volatile("cp.async.cg.shared.global [%0], [%1], 16, %2;" \
                 :: "r"(dst), "l"(src), "r"(sz) : "memory")
#define CP_COMMIT()  asm volatile("cp.async.commit_group;" ::: "memory")
#define CP_WAIT0()   asm volatile("cp.async.wait_group 0;" ::: "memory")

// ---------------- prep kernel 1: tables + batch ----------------
__global__ void k_prep1(const float* __restrict__ contour, const int* bi) {
    int bid = blockIdx.x;
    if (bid < NV * NC) {
        int v = bid & 127, c = bid >> 7, t = threadIdx.x;
        float cx = contour[(c * NV + v) * 2 + 0] * 0.25f;
        float cy = contour[(c * NV + v) * 2 + 1] * 0.25f;
        float dx = (float)t - cx, dy = (float)t - cy;
        const float INV2PI = 0.15915494309189535f;
        g_Fx[(c * NV + v) * WW + t] = INV2PI * __expf(-0.5f * dx * dx);
        g_Fy[(c * NV + v) * HH + t] = __expf(-0.5f * dy * dy);
    } else {
        __shared__ int s_is64;
        if (threadIdx.x == 0) {
            int is64 = 1;
            #pragma unroll
            for (int i = 0; i < 16; i++)
                if (bi[2 * i + 1] != 0) is64 = 0;
            s_is64 = is64;
        }
        __syncthreads();
        int t = threadIdx.x;
        if (t < NC) g_batch[t] = s_is64 ? bi[2 * t] : bi[t];
    }
}

// ---------------- fill kernel: vectorized shifted fill + misc --------------
// main fill threads = 3*8*64*130*16 = 3,194,880 -> /256 = 12480 blocks (exact)
// c0 zero: 24 planes * 16640 halves / 8 = 49,920 uint4 -> /256 = 195 blocks
// wsplit: NCH*16384 = 163,840 -> /256 = 640 blocks
// out-init: 262144 floats / 4 = 65,536 float4 -> /256 = 256 blocks
#define FILLA_BLOCKS 12480
#define C0Z_BLOCKS   195
#define WS_BLOCKS    640
#define OINIT_BLOCKS 256
__global__ void k_fill(const float* __restrict__ feat, const float* __restrict__ w1,
                       const float* __restrict__ b2, float* __restrict__ outp) {
    int bid = blockIdx.x;
    int tid = threadIdx.x;
    if (bid < FILLA_BLOCKS) {
        int idx = bid * 256 + tid;          // < 3*8*64*130*16
        int xg = idx & 15;                  // x-group of 8 halves
        int rest = idx >> 4;
        int yq = rest % 130;
        int rest2 = rest / 130;
        int ci = rest2 & 63;
        int rest3 = rest2 >> 6;
        int n = rest3 & 7;
        int kx = rest3 >> 3;
        uint16_t out8[8] = {0, 0, 0, 0, 0, 0, 0, 0};
        int y = yq - 1;
        if (y >= 0 && y < 128) {
            const float* src = feat + ((n * CIN + ci) * HH + y) * WW;
            int x0 = xg * 8 - 1 + kx;
            if (x0 >= 0 && x0 + 7 < 128) {
                #pragma unroll
                for (int j = 0; j < 8; j++)
                    out8[j] = __half_as_ushort(__float2half_rn(src[x0 + j]));
            } else {
                #pragma unroll
                for (int j = 0; j < 8; j++) {
                    int xs = x0 + j;
                    if (xs >= 0 && xs < 128)
                        out8[j] = __half_as_ushort(__float2half_rn(src[xs]));
                }
            }
        }
        *(uint4*)(g_Xs + kx * KXS + n * NS + (ci + 1) * CS + yq * 128 + xg * 8) =
            *(const uint4*)out8;
    } else if (bid < FILLA_BLOCKS + C0Z_BLOCKS) {
        int idx = (bid - FILLA_BLOCKS) * 256 + tid;   // < 24*2080
        int plane = idx / 2080;
        int pos = (idx - plane * 2080) * 8;
        int nn = plane & 7;
        int kx = plane >> 3;
        *(uint4*)(g_Xs + kx * KXS + nn * NS + pos) = make_uint4(0, 0, 0, 0);
    } else if (bid < FILLA_BLOCKS + C0Z_BLOCKS + WS_BLOCKS) {
        int idx = (bid - FILLA_BLOCKS - C0Z_BLOCKS) * 256 + tid;   // < NCH*16384
        int c = idx >> 14;
        int r = idx & 16383;
        int m = r >> 6, q = r & 63;
        int kg = c * CHUNK + q;
        float v = (kg < KREAL) ? w1[m * KREAL + kg] : 0.f;
        int off = m * 128 + q * 2;
        int sw = off ^ ((off >> 3) & 0x70);
        ((uint16_t*)g_wBh4)[c * 16384 + (sw >> 1)] =
            __half_as_ushort(__float2half_rn(v));
    } else {
        int idx = (bid - FILLA_BLOCKS - C0Z_BLOCKS - WS_BLOCKS) * 256 + tid;
        int o = (idx >> 12) & 1;            // float4 index -> output channel
        float v = b2[o];
        *(float4*)(outp + idx * 4) = make_float4(v, v, v, v);
    }
}

// ---------------- scattered = segment_sum of contour maps ----------------
__global__ void k_scatter(float* __restrict__ out_scat) {
    int n = blockIdx.y, y0 = blockIdx.x * 8, x = threadIdx.x;
    __shared__ float s_fy[NV][8];
    float acc[8];
    #pragma unroll
    for (int r = 0; r < 8; r++) acc[r] = 0.f;
    for (int c = 0; c < NC; c++) {
        if (g_batch[c] != n) continue;
        __syncthreads();
        for (int idx = x; idx < NV * 8; idx += 128) {
            int v = idx >> 3, r = idx & 7;
            s_fy[v][r] = g_Fy[(c * NV + v) * HH + (y0 + r)];
        }
        __syncthreads();
        const float* fxp = &g_Fx[(c * NV) * WW + x];
        #pragma unroll 4
        for (int v = 0; v < NV; v++) {
            float fx = fxp[v * WW];
            #pragma unroll
            for (int r = 0; r < 8; r++) acc[r] += fx * s_fy[v][r];
        }
    }
    #pragma unroll
    for (int r = 0; r < 8; r++) {
        out_scat[(n * HH + y0 + r) * WW + x] = acc[r];
        uint16_t v = __half_as_ushort(__float2half_rn(acc[r]));
        int base = n * NS + 0 * CS + (y0 + r + 1) * 128;
        #pragma unroll
        for (int kx = 0; kx < 3; kx++) {
            int xq = x + 1 - kx;
            if (xq >= 0 && xq < 128) g_Xs[kx * KXS + base + xq] = v;
        }
    }
}

// ---------------- HMMA conv kernel: CTA = (row, ch-half) -------------------
// A tile k-major [128 rows(k*2+h)][128B], cp.async-staged. ldmatrix.trans.
// dyn smem: A0 16K | A1 16K | B0 16K | B1 16K = 64KB. 2 CTAs/SM.
#define DSMEM_BYTES (65536 + 1024)

__global__ void __launch_bounds__(256, 2)
k_conv_mma(const float* __restrict__ b1, const float* __restrict__ w2,
           float* __restrict__ outp) {
    extern __shared__ char dsm[];
    __shared__ int   s_off[KPAD];
    __shared__ float s_b1[CMID / 2];
    __shared__ float s_w2[2 * CMID / 2];
    __shared__ float s_part[HH * 2];

    const int tid  = threadIdx.x;
    const int wid  = tid >> 5;
    const int lane = tid & 31;
    const int gid  = lane >> 2;       // 0..7
    const int tq   = lane & 3;        // 0..3
    const int wm   = wid >> 2;        // 0..1 (px half: 64 px)
    const int wn   = wid & 3;         // 0..3 (32 ch each)
    const int row  = blockIdx.x >> 1;
    const int ch   = blockIdx.x & 1;  // channel half
    const int n = row >> 7;
    const int y = row & 127;
    const int chbase = ch * 128;

    const uint32_t sbu = smem_u32(dsm);
    const uint32_t pad = (1024u - (sbu & 1023u)) & 1023u;
    const uint32_t base = sbu + pad;
    // A buffers: +buf*16384 ; B buffers: +32768 + buf*16384

    for (int i = tid; i < 128; i += 256) {
        s_b1[i] = b1[chbase + i];
        s_w2[i] = w2[chbase + i];
        s_w2[128 + i] = w2[CMID + chbase + i];
    }
    s_part[tid] = 0.f;
    for (int k = tid; k < KPAD; k += 256) {
        int off = -1;
        if (k < KREAL) {
            int ci = k / 9, pos = k - ci * 9;
            int ky = pos / 3, kx = pos - ky * 3;
            off = kx * KXS + ci * CS + ky * 128;
        }
        s_off[k] = off;
    }

    float acc[4][4][4];
    #pragma unroll
    for (int mt = 0; mt < 4; mt++)
        #pragma unroll
        for (int nt = 0; nt < 4; nt++)
            #pragma unroll
            for (int r = 0; r < 4; r++) acc[mt][nt][r] = 0.f;

    const int xbase = n * NS + y * 128;

    // ldmatrix.trans lane addressing for A (k-major tile)
    const int g8 = lane >> 3;
    const int j8 = lane & 7;
    const int koff8 = (g8 >> 1) * 8;
    const int clane = g8 & 1;
    const int rbase = (j8 + koff8) * 2 + wm;
    // B fragment addressing
    const int brow = lane & 7;
    const int bcolsel = ((lane >> 3) & 1) * 16;

#define STAGE_A(k0, aA)                                                        \
    do {                                                                       \
        _Pragma("unroll")                                                      \
        for (int t = 0; t < 4; t++) {                                          \
            int idx = tid + t * 256;                                           \
            int rowi = idx >> 3;               /* 0..127 = k*2+h */            \
            int c8 = idx & 7;                                                  \
            int k = rowi >> 1, h = rowi & 1;                                   \
            int off = s_off[(k0) + k];                                         \
            uint32_t sz = (off >= 0) ? 16u : 0u;                               \
            const uint16_t* src = g_Xs + (xbase + (off >= 0 ? off : 0)         \
                                          + h * 64 + c8 * 8);                  \
            uint32_t dst = (aA) + rowi * 128 + ((c8 ^ (rowi & 7)) << 4);       \
            CP_ASYNC16Z(dst, src, sz);                                         \
        }                                                                      \
    } while (0)

#define STAGE_B(c, aB)                                                         \
    do {                                                                       \
        const char* src = (const char*)(g_wBh4 + (c) * 2048 + ch * 1024);      \
        _Pragma("unroll")                                                      \
        for (int i = 0; i < 4; i++) {                                          \
            int gi = tid + i * 256;                                            \
            CP_ASYNC16((aB) + gi * 16, src + gi * 16);                         \
        }                                                                      \
    } while (0)

    __syncthreads();
    STAGE_A(0, base);
    STAGE_B(0, base + 32768u);
    CP_COMMIT();
    CP_WAIT0();
    __syncthreads();

    for (int c = 0; c < NCH; c++) {
        const int cur = c & 1;
        const uint32_t aA = base + (uint32_t)cur * 16384u;
        const uint32_t aB = base + 32768u + (uint32_t)cur * 16384u;

        if (c < NCH - 1) {
            const int nxt = cur ^ 1;
            STAGE_A((c + 1) * CHUNK, base + (uint32_t)nxt * 16384u);
            STAGE_B(c + 1, base + 32768u + (uint32_t)nxt * 16384u);
            CP_COMMIT();
        }

        const int nks = (c == NCH - 1) ? 1 : 4;
        #pragma unroll
        for (int ks = 0; ks < 4; ks++) {
            if (ks >= nks) break;
            const int kcol = ks * 32;
            uint32_t Af[4][4];
            #pragma unroll
            for (int mt = 0; mt < 4; mt++) {
                int r0 = rbase + ks * 32;
                int chunk = mt * 2 + clane;
                uint32_t ad = aA + (uint32_t)(r0 * 128 + ((chunk ^ (r0 & 7)) << 4));
                ldm_x4_trans(Af[mt], ad);
            }
            uint32_t Bf[4][2];
            #pragma unroll
            for (int nt = 0; nt < 4; nt++) {
                int rowb = wn * 32 + nt * 8 + brow;
                int colb = kcol + bcolsel;
                uint32_t bd = aB + (uint32_t)(rowb * 128 + (colb ^ ((rowb & 7) * 16)));
                ldm_x2(Bf[nt], bd);
            }
            #pragma unroll
            for (int nt = 0; nt < 4; nt++)
                #pragma unroll
                for (int mt = 0; mt < 4; mt++)
                    mma_fp16(acc[mt][nt], Af[mt], Bf[nt]);
        }
        CP_WAIT0();
        __syncthreads();
    }

    // epilogue: relu(D + b1) -> partial 1x1 conv, reduce in smem, atomicAdd gmem
    #pragma unroll
    for (int mt = 0; mt < 4; mt++) {
        #pragma unroll
        for (int half = 0; half < 2; half++) {
            float s0 = 0.f, s1 = 0.f;
            #pragma unroll
            for (int nt = 0; nt < 4; nt++) {
                int cl = wn * 32 + nt * 8 + tq * 2;
                float h0 = fmaxf(acc[mt][nt][half * 2 + 0] + s_b1[cl], 0.f);
                float h1 = fmaxf(acc[mt][nt][half * 2 + 1] + s_b1[cl + 1], 0.f);
                s0 += h0 * s_w2[cl] + h1 * s_w2[cl + 1];
                s1 += h0 * s_w2[128 + cl] + h1 * s_w2[128 + cl + 1];
            }
            s0 += __shfl_xor_sync(0xffffffffu, s0, 1);
            s0 += __shfl_xor_sync(0xffffffffu, s0, 2);
            s1 += __shfl_xor_sync(0xffffffffu, s1, 1);
            s1 += __shfl_xor_sync(0xffffffffu, s1, 2);
            if (tq == 0) {
                int px = wm * 64 + mt * 16 + half * 8 + gid;
                atomicAdd(&s_part[px * 2 + 0], s0);
                atomicAdd(&s_part[px * 2 + 1], s1);
            }
        }
    }
    __syncthreads();
    {
        int px = tid >> 1, o = tid & 1;
        atomicAdd(&outp[((n * 2 + o) * HH + y) * WW + px], s_part[px * 2 + o]);
    }
}

// ---------------- launch ----------------
extern "C" void kernel_launch(void* const* d_in, const int* in_sizes, int n_in,
                              void* d_out, int out_size) {
    const float* contour = (const float*)d_in[0];
    const float* feature = (const float*)d_in[1];
    const int*   batchi  = (const int*)d_in[2];
    const float* w1      = (const float*)d_in[3];
    const float* b1      = (const float*)d_in[4];
    const float* w2      = (const float*)d_in[5];
    const float* b2      = (const float*)d_in[6];
    float* out = (float*)d_out;
    float* out_scat = out + NIMG * 2 * HH * WW;

    static int attr_set = 0;
    if (!attr_set) {
        cudaFuncSetAttribute(k_conv_mma,
                             cudaFuncAttributeMaxDynamicSharedMemorySize,
                             DSMEM_BYTES);
        attr_set = 1;
    }

    k_prep1<<<NV * NC + 1, 128>>>(contour, batchi);
    k_fill<<<FILLA_BLOCKS + C0Z_BLOCKS + WS_BLOCKS + OINIT_BLOCKS, 256>>>(
        feature, w1, b2, out);
    k_scatter<<<dim3(HH / 8, NIMG), 128>>>(out_scat);
    k_conv_mma<<<2048, 256, DSMEM_BYTES>>>(b1, w2, out);
}

// round 15
// speedup vs baseline: 1.1351x; 1.1351x over previous
#include <cuda_runtime.h>
#include <cuda_fp16.h>
#include <cstdint>

// ---------------- problem constants ----------------
#define NIMG 8
#define NC   32
#define NV   128
#define HH   128
#define WW   128
#define CIN  64
#define CC   65
#define CMID 256
#define HP   130
#define KREAL 585          // 65 * 9, k = ci*9 + ky*3 + kx
#define KPAD  640
#define CHUNK 64
#define NCH   10

// shifted-input buffer strides (fp16 elements); rows are 128 wide, 130 tall
#define CS  (HP * 128)           // per channel  = 16640
#define NS  (CC * CS)            // per image    = 1081600
#define KXS (NIMG * NS)          // per kx shift = 8652800

// ---------------- device scratch ----------------
__device__ float    g_Fx[NC * NV * WW];
__device__ float    g_Fy[NC * NV * HH];
__device__ uint16_t g_Xs[3 * KXS];       // 3 kx-shifted fp16 padded inputs (52MB)
__device__ uint4    g_wBh4[NCH * 2048];  // pre-swizzled fp16 weight planes
__device__ int      g_batch[NC];

// ---------------- helpers ----------------
__device__ __forceinline__ uint32_t smem_u32(const void* p) {
    uint32_t a;
    asm("{ .reg .u64 t; cvta.to.shared.u64 t, %1; cvt.u32.u64 %0, t; }"
        : "=r"(a) : "l"(p));
    return a;
}
__device__ __forceinline__ void ldm_x4_trans(uint32_t* r, uint32_t a) {
    asm volatile("ldmatrix.sync.aligned.m8n8.x4.trans.shared.b16 {%0,%1,%2,%3}, [%4];"
        : "=r"(r[0]), "=r"(r[1]), "=r"(r[2]), "=r"(r[3]) : "r"(a));
}
__device__ __forceinline__ void ldm_x4(uint32_t* r, uint32_t a) {
    asm volatile("ldmatrix.sync.aligned.m8n8.x4.shared.b16 {%0,%1,%2,%3}, [%4];"
        : "=r"(r[0]), "=r"(r[1]), "=r"(r[2]), "=r"(r[3]) : "r"(a));
}
__device__ __forceinline__ void mma_fp16(float* d, const uint32_t* a, const uint32_t* b) {
    asm volatile("mma.sync.aligned.m16n8k16.row.col.f32.f16.f16.f32 "
        "{%0,%1,%2,%3}, {%4,%5,%6,%7}, {%8,%9}, {%0,%1,%2,%3};"
        : "+f"(d[0]), "+f"(d[1]), "+f"(d[2]), "+f"(d[3])
        : "r"(a[0]), "r"(a[1]), "r"(a[2]), "r"(a[3]), "r"(b[0]), "r"(b[1]));
}
#define CP_ASYNC16(dst, src) \
    asm volatile("cp.async.cg.shared.global [%0], [%1], 16;" \
                 :: "r"(dst), "l"(src) : "memory")
#define CP_ASYNC16Z(dst, src, sz) \
    asm volatile("cp.async.cg.shared.global [%0], [%1], 16, %2;" \
                 :: "r"(dst), "l"(src), "r"(sz) : "memory")
#define CP_COMMIT()  asm volatile("cp.async.commit_group;" ::: "memory")
#define CP_WAIT0()   asm volatile("cp.async.wait_group 0;" ::: "memory")

// ---------------- prep kernel 1: tables + batch ----------------
__global__ void k_prep1(const float* __restrict__ contour, const int* bi) {
    int bid = blockIdx.x;
    if (bid < NV * NC) {
        int v = bid & 127, c = bid >> 7, t = threadIdx.x;
        float cx = contour[(c * NV + v) * 2 + 0] * 0.25f;
        float cy = contour[(c * NV + v) * 2 + 1] * 0.25f;
        float dx = (float)t - cx, dy = (float)t - cy;
        const float INV2PI = 0.15915494309189535f;
        g_Fx[(c * NV + v) * WW + t] = INV2PI * __expf(-0.5f * dx * dx);
        g_Fy[(c * NV + v) * HH + t] = __expf(-0.5f * dy * dy);
    } else {
        __shared__ int s_is64;
        if (threadIdx.x == 0) {
            int is64 = 1;
            #pragma unroll
            for (int i = 0; i < 16; i++)
                if (bi[2 * i + 1] != 0) is64 = 0;
            s_is64 = is64;
        }
        __syncthreads();
        int t = threadIdx.x;
        if (t < NC) g_batch[t] = s_is64 ? bi[2 * t] : bi[t];
    }
}

// ---------------- prep kernel 2 (R10-exact, measured 95us prep) ------------
#define FILL_BLOCKS 2048
#define ZERO_BLOCKS 2089         // (399360 + 2*67600 + 255)/256
#define WS_BLOCKS 640
#define OINIT_BLOCKS 1024
__global__ void k_prep2(const float* __restrict__ feat, const float* __restrict__ w1,
                        const float* __restrict__ b2, float* __restrict__ outp) {
    int bid = blockIdx.x;
    int tid = threadIdx.x;
    if (bid < FILL_BLOCKS) {
        // feature -> 3 kx-shifted fp16 buffers (channels 1..64)
        const int total = NIMG * CIN * HH * WW;
        for (int idx = bid * 256 + tid; idx < total; idx += FILL_BLOCKS * 256) {
            int x = idx & 127;
            int y = (idx >> 7) & 127;
            int ci = (idx >> 14) & 63;
            int n = idx >> 20;
            uint16_t v = __half_as_ushort(__float2half_rn(feat[idx]));
            int base = n * NS + (ci + 1) * CS + (y + 1) * 128;
            #pragma unroll
            for (int kx = 0; kx < 3; kx++) {
                int xq = x + 1 - kx;
                if (xq >= 0 && xq < 128) g_Xs[kx * KXS + base + xq] = v;
            }
        }
    } else if (bid < FILL_BLOCKS + ZERO_BLOCKS) {
        int idx = (bid - FILL_BLOCKS) * 256 + tid;
        if (idx < 399360) {
            // top/bottom pad rows of every (kx, n, c) plane
            int x = idx & 127;
            int rr = idx >> 7;                 // 0..3119
            int yy = (rr & 1) ? 129 : 0;
            int kxnc = rr >> 1;                // 0..1559
            int c = kxnc % 65;
            int nn = (kxnc / 65) & 7;
            int kx = kxnc / (65 * 8);
            g_Xs[kx * KXS + nn * NS + c * CS + yy * 128 + x] = 0;
        } else if (idx < 399360 + 2 * 67600) {
            // left edge of buf kx=0 (x=0) and right edge of buf kx=2 (x=127)
            int j = idx - 399360;
            int set = j / 67600;
            int jj = j % 67600;
            int yy = jj % 130;
            int c = (jj / 130) % 65;
            int nn = jj / (130 * 65);
            int kx = set ? 2 : 0;
            int x = set ? 127 : 0;
            g_Xs[kx * KXS + nn * NS + c * CS + yy * 128 + x] = 0;
        }
    } else if (bid < FILL_BLOCKS + ZERO_BLOCKS + WS_BLOCKS) {
        int idx = (bid - FILL_BLOCKS - ZERO_BLOCKS) * 256 + tid;   // < NCH*16384
        int c = idx >> 14;
        int r = idx & 16383;
        int m = r >> 6, q = r & 63;
        int kg = c * CHUNK + q;
        float v = (kg < KREAL) ? w1[m * KREAL + kg] : 0.f;
        int off = m * 128 + q * 2;
        int sw = off ^ ((off >> 3) & 0x70);
        ((uint16_t*)g_wBh4)[c * 16384 + (sw >> 1)] =
            __half_as_ushort(__float2half_rn(v));
    } else {
        int idx = (bid - FILL_BLOCKS - ZERO_BLOCKS - WS_BLOCKS) * 256 + tid;
        int o = (idx >> 14) & 1;
        outp[idx] = b2[o];
    }
}

// ---------------- scattered = segment_sum of contour maps ----------------
__global__ void k_scatter(float* __restrict__ out_scat) {
    int n = blockIdx.y, y0 = blockIdx.x * 8, x = threadIdx.x;
    __shared__ float s_fy[NV][8];
    float acc[8];
    #pragma unroll
    for (int r = 0; r < 8; r++) acc[r] = 0.f;
    for (int c = 0; c < NC; c++) {
        if (g_batch[c] != n) continue;
        __syncthreads();
        for (int idx = x; idx < NV * 8; idx += 128) {
            int v = idx >> 3, r = idx & 7;
            s_fy[v][r] = g_Fy[(c * NV + v) * HH + (y0 + r)];
        }
        __syncthreads();
        const float* fxp = &g_Fx[(c * NV) * WW + x];
        #pragma unroll 4
        for (int v = 0; v < NV; v++) {
            float fx = fxp[v * WW];
            #pragma unroll
            for (int r = 0; r < 8; r++) acc[r] += fx * s_fy[v][r];
        }
    }
    #pragma unroll
    for (int r = 0; r < 8; r++) {
        out_scat[(n * HH + y0 + r) * WW + x] = acc[r];
        uint16_t v = __half_as_ushort(__float2half_rn(acc[r]));
        int base = n * NS + 0 * CS + (y0 + r + 1) * 128;
        #pragma unroll
        for (int kx = 0; kx < 3; kx++) {
            int xq = x + 1 - kx;
            if (xq >= 0 && xq < 128) g_Xs[kx * KXS + base + xq] = v;
        }
    }
}

// ---------------- HMMA conv kernel: CTA = (row, ch-half) -------------------
// A tile k-major [128 rows(k*2+h)][128B], cp.async-staged. ldmatrix.trans.
// dyn smem: A0 16K | A1 16K | B0 16K | B1 16K = 64KB. 2 CTAs/SM.
#define DSMEM_BYTES (65536 + 1024)

__global__ void __launch_bounds__(256, 2)
k_conv_mma(const float* __restrict__ b1, const float* __restrict__ w2,
           float* __restrict__ outp) {
    extern __shared__ char dsm[];
    __shared__ int   s_off[KPAD];
    __shared__ float s_b1[CMID / 2];
    __shared__ float s_w2[2 * CMID / 2];
    __shared__ float s_part[HH * 2];

    const int tid  = threadIdx.x;
    const int wid  = tid >> 5;
    const int lane = tid & 31;
    const int gid  = lane >> 2;       // 0..7
    const int tq   = lane & 3;        // 0..3
    const int wm   = wid >> 2;        // 0..1 (px half: 64 px)
    const int wn   = wid & 3;         // 0..3 (32 ch each)
    const int row  = blockIdx.x >> 1;
    const int ch   = blockIdx.x & 1;  // channel half
    const int n = row >> 7;
    const int y = row & 127;
    const int chbase = ch * 128;

    const uint32_t sbu = smem_u32(dsm);
    const uint32_t pad = (1024u - (sbu & 1023u)) & 1023u;
    const uint32_t base = sbu + pad;
    // A buffers: +buf*16384 ; B buffers: +32768 + buf*16384

    for (int i = tid; i < 128; i += 256) {
        s_b1[i] = b1[chbase + i];
        s_w2[i] = w2[chbase + i];
        s_w2[128 + i] = w2[CMID + chbase + i];
    }
    s_part[tid] = 0.f;
    for (int k = tid; k < KPAD; k += 256) {
        int off = -1;
        if (k < KREAL) {
            int ci = k / 9, pos = k - ci * 9;
            int ky = pos / 3, kx = pos - ky * 3;
            off = kx * KXS + ci * CS + ky * 128;
        }
        s_off[k] = off;
    }

    float acc[4][4][4];
    #pragma unroll
    for (int mt = 0; mt < 4; mt++)
        #pragma unroll
        for (int nt = 0; nt < 4; nt++)
            #pragma unroll
            for (int r = 0; r < 4; r++) acc[mt][nt][r] = 0.f;

    const int xbase = n * NS + y * 128;

    // ldmatrix.trans lane addressing for A (k-major tile)
    const int g8 = lane >> 3;
    const int j8 = lane & 7;
    const int koff8 = (g8 >> 1) * 8;
    const int clane = g8 & 1;
    const int rbase = (j8 + koff8) * 2 + wm;
    // B x4 fragment addressing: lanes 0-7 m0, 8-15 m1, 16-23 m2, 24-31 m3
    // m0=(ntp,kcol+0) m1=(ntp,kcol+16) m2=(ntp+8rows,kcol+0) m3=(ntp+8,kcol+16)
    const int browx4 = (lane & 7) + ((lane >> 4) << 3);
    const int bcolsel = ((lane >> 3) & 1) * 16;

#define STAGE_A(k0, aA)                                                        \
    do {                                                                       \
        _Pragma("unroll")                                                      \
        for (int t = 0; t < 4; t++) {                                          \
            int idx = tid + t * 256;                                           \
            int rowi = idx >> 3;               /* 0..127 = k*2+h */            \
            int c8 = idx & 7;                                                  \
            int k = rowi >> 1, h = rowi & 1;                                   \
            int off = s_off[(k0) + k];                                         \
            uint32_t sz = (off >= 0) ? 16u : 0u;                               \
            const uint16_t* src = g_Xs + (xbase + (off >= 0 ? off : 0)         \
                                          + h * 64 + c8 * 8);                  \
            uint32_t dst = (aA) + rowi * 128 + ((c8 ^ (rowi & 7)) << 4);       \
            CP_ASYNC16Z(dst, src, sz);                                         \
        }                                                                      \
    } while (0)

#define STAGE_B(c, aB)                                                         \
    do {                                                                       \
        const char* src = (const char*)(g_wBh4 + (c) * 2048 + ch * 1024);      \
        _Pragma("unroll")                                                      \
        for (int i = 0; i < 4; i++) {                                          \
            int gi = tid + i * 256;                                            \
            CP_ASYNC16((aB) + gi * 16, src + gi * 16);                         \
        }                                                                      \
    } while (0)

    __syncthreads();
    STAGE_A(0, base);
    STAGE_B(0, base + 32768u);
    CP_COMMIT();
    CP_WAIT0();
    __syncthreads();

    for (int c = 0; c < NCH; c++) {
        const int cur = c & 1;
        const uint32_t aA = base + (uint32_t)cur * 16384u;
        const uint32_t aB = base + 32768u + (uint32_t)cur * 16384u;

        if (c < NCH - 1) {
            const int nxt = cur ^ 1;
            STAGE_A((c + 1) * CHUNK, base + (uint32_t)nxt * 16384u);
            STAGE_B(c + 1, base + 32768u + (uint32_t)nxt * 16384u);
            CP_COMMIT();
        }

        const int nks = (c == NCH - 1) ? 1 : 4;
        #pragma unroll
        for (int ks = 0; ks < 4; ks++) {
            if (ks >= nks) break;
            const int kcol = ks * 32;
            uint32_t Af[4][4];
            #pragma unroll
            for (int mt = 0; mt < 4; mt++) {
                int r0 = rbase + ks * 32;
                int chunk = mt * 2 + clane;
                uint32_t ad = aA + (uint32_t)(r0 * 128 + ((chunk ^ (r0 & 7)) << 4));
                ldm_x4_trans(Af[mt], ad);
            }
            // B: 2 x4 loads cover nt=0..3 (pairs of 8-row blocks)
            uint32_t Bf[2][4];
            #pragma unroll
            for (int p = 0; p < 2; p++) {
                int rowb = wn * 32 + p * 16 + browx4;
                int colb = kcol + bcolsel;
                uint32_t bd = aB + (uint32_t)(rowb * 128 + (colb ^ ((rowb & 7) * 16)));
                ldm_x4(Bf[p], bd);
            }
            #pragma unroll
            for (int p = 0; p < 2; p++)
                #pragma unroll
                for (int q = 0; q < 2; q++)
                    #pragma unroll
                    for (int mt = 0; mt < 4; mt++)
                        mma_fp16(acc[mt][p * 2 + q], Af[mt], &Bf[p][q * 2]);
        }
        CP_WAIT0();
        __syncthreads();
    }

    // epilogue: relu(D + b1) -> partial 1x1 conv, reduce in smem, atomicAdd gmem
    #pragma unroll
    for (int mt = 0; mt < 4; mt++) {
        #pragma unroll
        for (int half = 0; half < 2; half++) {
            float s0 = 0.f, s1 = 0.f;
            #pragma unroll
            for (int nt = 0; nt < 4; nt++) {
                int cl = wn * 32 + nt * 8 + tq * 2;
                float h0 = fmaxf(acc[mt][nt][half * 2 + 0] + s_b1[cl], 0.f);
                float h1 = fmaxf(acc[mt][nt][half * 2 + 1] + s_b1[cl + 1], 0.f);
                s0 += h0 * s_w2[cl] + h1 * s_w2[cl + 1];
                s1 += h0 * s_w2[128 + cl] + h1 * s_w2[128 + cl + 1];
            }
            s0 += __shfl_xor_sync(0xffffffffu, s0, 1);
            s0 += __shfl_xor_sync(0xffffffffu, s0, 2);
            s1 += __shfl_xor_sync(0xffffffffu, s1, 1);
            s1 += __shfl_xor_sync(0xffffffffu, s1, 2);
            if (tq == 0) {
                int px = wm * 64 + mt * 16 + half * 8 + gid;
                atomicAdd(&s_part[px * 2 + 0], s0);
                atomicAdd(&s_part[px * 2 + 1], s1);
            }
        }
    }
    __syncthreads();
    {
        int px = tid >> 1, o = tid & 1;
        atomicAdd(&outp[((n * 2 + o) * HH + y) * WW + px], s_part[px * 2 + o]);
    }
}

// ---------------- launch ----------------
extern "C" void kernel_launch(void* const* d_in, const int* in_sizes, int n_in,
                              void* d_out, int out_size) {
    const float* contour = (const float*)d_in[0];
    const float* feature = (const float*)d_in[1];
    const int*   batchi  = (const int*)d_in[2];
    const float* w1      = (const float*)d_in[3];
    const float* b1      = (const float*)d_in[4];
    const float* w2      = (const float*)d_in[5];
    const float* b2      = (const float*)d_in[6];
    float* out = (float*)d_out;
    float* out_scat = out + NIMG * 2 * HH * WW;

    static int attr_set = 0;
    if (!attr_set) {
        cudaFuncSetAttribute(k_conv_mma,
                             cudaFuncAttributeMaxDynamicSharedMemorySize,
                             DSMEM_BYTES);
        attr_set = 1;
    }

    k_prep1<<<NV * NC + 1, 128>>>(contour, batchi);
    k_prep2<<<FILL_BLOCKS + ZERO_BLOCKS + WS_BLOCKS + OINIT_BLOCKS, 256>>>(
        feature, w1, b2, out);
    k_scatter<<<dim3(HH / 8, NIMG), 128>>>(out_scat);
    k_conv_mma<<<2048, 256, DSMEM_BYTES>>>(b1, w2, out);
}

// round 16
// speedup vs baseline: 1.3860x; 1.2211x over previous
#include <cuda_runtime.h>
#include <cuda_fp16.h>
#include <cstdint>

// ---------------- problem constants ----------------
#define NIMG 8
#define NC   32
#define NV   128
#define HH   128
#define WW   128
#define CIN  64
#define CC   65
#define CMID 256
#define HP   130
#define KREAL 585          // 65 * 9, k = ci*9 + ky*3 + kx
#define KPAD  640
#define CHUNK 64
#define NCH   10

// shifted-input buffer strides (fp16 elements); rows are 128 wide, 130 tall
#define CS  (HP * 128)           // per channel  = 16640
#define NS  (CC * CS)            // per image    = 1081600
#define KXS (NIMG * NS)          // per kx shift = 8652800

// ---------------- device scratch ----------------
__device__ float    g_Fx[NC * NV * WW];
__device__ float    g_Fy[NC * NV * HH];
__device__ uint16_t g_Xs[3 * KXS];       // 3 kx-shifted fp16 padded inputs (52MB)
__device__ uint4    g_wBh4[NCH * 2048];  // pre-swizzled fp16 weight planes
__device__ int      g_batch[NC];

// ---------------- helpers ----------------
__device__ __forceinline__ uint32_t smem_u32(const void* p) {
    uint32_t a;
    asm("{ .reg .u64 t; cvta.to.shared.u64 t, %1; cvt.u32.u64 %0, t; }"
        : "=r"(a) : "l"(p));
    return a;
}
__device__ __forceinline__ void ldm_x4_trans(uint32_t* r, uint32_t a) {
    asm volatile("ldmatrix.sync.aligned.m8n8.x4.trans.shared.b16 {%0,%1,%2,%3}, [%4];"
        : "=r"(r[0]), "=r"(r[1]), "=r"(r[2]), "=r"(r[3]) : "r"(a));
}
__device__ __forceinline__ void ldm_x4(uint32_t* r, uint32_t a) {
    asm volatile("ldmatrix.sync.aligned.m8n8.x4.shared.b16 {%0,%1,%2,%3}, [%4];"
        : "=r"(r[0]), "=r"(r[1]), "=r"(r[2]), "=r"(r[3]) : "r"(a));
}
__device__ __forceinline__ void mma_fp16(float* d, const uint32_t* a, const uint32_t* b) {
    asm volatile("mma.sync.aligned.m16n8k16.row.col.f32.f16.f16.f32 "
        "{%0,%1,%2,%3}, {%4,%5,%6,%7}, {%8,%9}, {%0,%1,%2,%3};"
        : "+f"(d[0]), "+f"(d[1]), "+f"(d[2]), "+f"(d[3])
        : "r"(a[0]), "r"(a[1]), "r"(a[2]), "r"(a[3]), "r"(b[0]), "r"(b[1]));
}
#define CP_ASYNC16(dst, src) \
    asm volatile("cp.async.cg.shared.global [%0], [%1], 16;" \
                 :: "r"(dst), "l"(src) : "memory")
#define CP_ASYNC16Z(dst, src, sz) \
    asm volatile("cp.async.cg.shared.global [%0], [%1], 16, %2;" \
                 :: "r"(dst), "l"(src), "r"(sz) : "memory")
#define CP_COMMIT()  asm volatile("cp.async.commit_group;" ::: "memory")
#define CP_WAIT0()   asm volatile("cp.async.wait_group 0;" ::: "memory")

// ---------------- prep kernel 1: tables + batch ----------------
__global__ void k_prep1(const float* __restrict__ contour, const int* bi) {
    int bid = blockIdx.x;
    if (bid < NV * NC) {
        int v = bid & 127, c = bid >> 7, t = threadIdx.x;
        float cx = contour[(c * NV + v) * 2 + 0] * 0.25f;
        float cy = contour[(c * NV + v) * 2 + 1] * 0.25f;
        float dx = (float)t - cx, dy = (float)t - cy;
        const float INV2PI = 0.15915494309189535f;
        g_Fx[(c * NV + v) * WW + t] = INV2PI * __expf(-0.5f * dx * dx);
        g_Fy[(c * NV + v) * HH + t] = __expf(-0.5f * dy * dy);
    } else {
        __shared__ int s_is64;
        if (threadIdx.x == 0) {
            int is64 = 1;
            #pragma unroll
            for (int i = 0; i < 16; i++)
                if (bi[2 * i + 1] != 0) is64 = 0;
            s_is64 = is64;
        }
        __syncthreads();
        int t = threadIdx.x;
        if (t < NC) g_batch[t] = s_is64 ? bi[2 * t] : bi[t];
    }
}

// ---------------- prep kernel 2 (R10-exact fill, measured fast) ------------
#define FILL_BLOCKS 2048
#define ZERO_BLOCKS 2089         // (399360 + 2*67600 + 255)/256
#define WS_BLOCKS 640
#define OINIT_BLOCKS 1024
__global__ void k_prep2(const float* __restrict__ feat, const float* __restrict__ w1,
                        const float* __restrict__ b2, float* __restrict__ outp) {
    int bid = blockIdx.x;
    int tid = threadIdx.x;
    if (bid < FILL_BLOCKS) {
        const int total = NIMG * CIN * HH * WW;
        for (int idx = bid * 256 + tid; idx < total; idx += FILL_BLOCKS * 256) {
            int x = idx & 127;
            int y = (idx >> 7) & 127;
            int ci = (idx >> 14) & 63;
            int n = idx >> 20;
            uint16_t v = __half_as_ushort(__float2half_rn(feat[idx]));
            int base = n * NS + (ci + 1) * CS + (y + 1) * 128;
            #pragma unroll
            for (int kx = 0; kx < 3; kx++) {
                int xq = x + 1 - kx;
                if (xq >= 0 && xq < 128) g_Xs[kx * KXS + base + xq] = v;
            }
        }
    } else if (bid < FILL_BLOCKS + ZERO_BLOCKS) {
        int idx = (bid - FILL_BLOCKS) * 256 + tid;
        if (idx < 399360) {
            int x = idx & 127;
            int rr = idx >> 7;
            int yy = (rr & 1) ? 129 : 0;
            int kxnc = rr >> 1;
            int c = kxnc % 65;
            int nn = (kxnc / 65) & 7;
            int kx = kxnc / (65 * 8);
            g_Xs[kx * KXS + nn * NS + c * CS + yy * 128 + x] = 0;
        } else if (idx < 399360 + 2 * 67600) {
            int j = idx - 399360;
            int set = j / 67600;
            int jj = j % 67600;
            int yy = jj % 130;
            int c = (jj / 130) % 65;
            int nn = jj / (130 * 65);
            int kx = set ? 2 : 0;
            int x = set ? 127 : 0;
            g_Xs[kx * KXS + nn * NS + c * CS + yy * 128 + x] = 0;
        }
    } else if (bid < FILL_BLOCKS + ZERO_BLOCKS + WS_BLOCKS) {
        int idx = (bid - FILL_BLOCKS - ZERO_BLOCKS) * 256 + tid;   // < NCH*16384
        int c = idx >> 14;
        int r = idx & 16383;
        int m = r >> 6, q = r & 63;
        int kg = c * CHUNK + q;
        float v = (kg < KREAL) ? w1[m * KREAL + kg] : 0.f;
        int off = m * 128 + q * 2;
        int sw = off ^ ((off >> 3) & 0x70);
        ((uint16_t*)g_wBh4)[c * 16384 + (sw >> 1)] =
            __half_as_ushort(__float2half_rn(v));
    } else {
        int idx = (bid - FILL_BLOCKS - ZERO_BLOCKS - WS_BLOCKS) * 256 + tid;
        int o = (idx >> 14) & 1;
        outp[idx] = b2[o];
    }
}

// ---------------- scattered = segment_sum (smem-tiled Fx) ----------------
__global__ void k_scatter(float* __restrict__ out_scat) {
    int n = blockIdx.y, y0 = blockIdx.x * 8, x = threadIdx.x;
    __shared__ float s_fy[NV][8];
    __shared__ float s_fx[32][128];
    float acc[8];
    #pragma unroll
    for (int r = 0; r < 8; r++) acc[r] = 0.f;
    for (int c = 0; c < NC; c++) {
        if (g_batch[c] != n) continue;
        __syncthreads();
        for (int idx = x; idx < NV * 8; idx += 128) {
            int v = idx >> 3, r = idx & 7;
            s_fy[v][r] = g_Fy[(c * NV + v) * HH + (y0 + r)];
        }
        for (int vb = 0; vb < 4; vb++) {
            __syncthreads();
            // coalesced load of 32 v-rows of Fx
            for (int i = 0; i < 32; i++)
                s_fx[i][x] = g_Fx[(c * NV + vb * 32 + i) * WW + x];
            __syncthreads();
            #pragma unroll 4
            for (int vv = 0; vv < 32; vv++) {
                float fx = s_fx[vv][x];
                int v = vb * 32 + vv;
                #pragma unroll
                for (int r = 0; r < 8; r++) acc[r] += fx * s_fy[v][r];
            }
        }
    }
    #pragma unroll
    for (int r = 0; r < 8; r++) {
        out_scat[(n * HH + y0 + r) * WW + x] = acc[r];
        uint16_t v = __half_as_ushort(__float2half_rn(acc[r]));
        int base = n * NS + 0 * CS + (y0 + r + 1) * 128;
        #pragma unroll
        for (int kx = 0; kx < 3; kx++) {
            int xq = x + 1 - kx;
            if (xq >= 0 && xq < 128) g_Xs[kx * KXS + base + xq] = v;
        }
    }
}

// ---------------- HMMA conv kernel: CTA = (row, px-half, ch-half) ----------
// D[64 px, 128 ch] per CTA; 4 CTAs/SM. A 8KB x2, B 16KB x2 = 48KB dyn smem.
#define DSMEM_BYTES (49152 + 1024)

__global__ void __launch_bounds__(256, 4)
k_conv_mma(const float* __restrict__ b1, const float* __restrict__ w2,
           float* __restrict__ outp) {
    extern __shared__ char dsm[];
    __shared__ int   s_off[KPAD];
    __shared__ float s_b1[128];
    __shared__ float s_w2[256];
    __shared__ float s_part[64 * 2];

    const int tid  = threadIdx.x;
    const int wid  = tid >> 5;
    const int lane = tid & 31;
    const int gid  = lane >> 2;       // 0..7
    const int tq   = lane & 3;        // 0..3
    const int wm   = wid >> 2;        // 0..1 (px 32-block)
    const int wn   = wid & 3;         // 0..3 (32 ch each)
    const int bid  = blockIdx.x;
    const int row  = bid >> 2;
    const int ph   = (bid >> 1) & 1;  // px half (64 px)
    const int chh  = bid & 1;         // ch half (128 ch)
    const int n = row >> 7;
    const int y = row & 127;
    const int chbase = chh * 128;

    const uint32_t sbu = smem_u32(dsm);
    const uint32_t pad = (1024u - (sbu & 1023u)) & 1023u;
    const uint32_t base = sbu + pad;
    // A buffers: +buf*8192 ; B buffers: +16384 + buf*16384

    for (int i = tid; i < 128; i += 256) {
        s_b1[i] = b1[chbase + i];
        s_w2[i] = w2[chbase + i];
        s_w2[128 + i] = w2[CMID + chbase + i];
    }
    if (tid < 128) s_part[tid] = 0.f;
    for (int k = tid; k < KPAD; k += 256) {
        int off = -1;
        if (k < KREAL) {
            int ci = k / 9, pos = k - ci * 9;
            int ky = pos / 3, kx = pos - ky * 3;
            off = kx * KXS + ci * CS + ky * 128;
        }
        s_off[k] = off;
    }

    float acc[2][4][4];
    #pragma unroll
    for (int mt = 0; mt < 2; mt++)
        #pragma unroll
        for (int nt = 0; nt < 4; nt++)
            #pragma unroll
            for (int r = 0; r < 4; r++) acc[mt][nt][r] = 0.f;

    const int xbase = n * NS + y * 128 + ph * 64;

    // ldmatrix.trans lane addressing for A (k-major tile, row = k)
    const int g8 = lane >> 3;
    const int j8 = lane & 7;
    const int koff8 = (g8 >> 1) * 8;
    const int clane = g8 & 1;          // px 8-block within 16
    const int rbase = j8 + koff8;      // k row for ks=0
    // B x4 fragment addressing
    const int browx4 = (lane & 7) + ((lane >> 4) << 3);
    const int bcolsel = ((lane >> 3) & 1) * 16;

    // A staging: 64 rows(k) x 8 c8 = 512 cp.async, 2 per thread
#define STAGE_A(k0, aA)                                                        \
    do {                                                                       \
        _Pragma("unroll")                                                      \
        for (int t = 0; t < 2; t++) {                                          \
            int idx = tid + t * 256;                                           \
            int rowi = idx >> 3;               /* 0..63 = k */                 \
            int c8 = idx & 7;                                                  \
            int off = s_off[(k0) + rowi];                                      \
            uint32_t sz = (off >= 0) ? 16u : 0u;                               \
            const uint16_t* src = g_Xs + (xbase + (off >= 0 ? off : 0)         \
                                          + c8 * 8);                           \
            uint32_t dst = (aA) + rowi * 128 + ((c8 ^ (rowi & 7)) << 4);       \
            CP_ASYNC16Z(dst, src, sz);                                         \
        }                                                                      \
    } while (0)

#define STAGE_B(c, aB)                                                         \
    do {                                                                       \
        const char* src = (const char*)(g_wBh4 + (c) * 2048 + chh * 1024);     \
        _Pragma("unroll")                                                      \
        for (int i = 0; i < 4; i++) {                                          \
            int gi = tid + i * 256;                                            \
            CP_ASYNC16((aB) + gi * 16, src + gi * 16);                         \
        }                                                                      \
    } while (0)

    __syncthreads();
    STAGE_A(0, base);
    STAGE_B(0, base + 16384u);
    CP_COMMIT();
    CP_WAIT0();
    __syncthreads();

    for (int c = 0; c < NCH; c++) {
        const int cur = c & 1;
        const uint32_t aA = base + (uint32_t)cur * 8192u;
        const uint32_t aB = base + 16384u + (uint32_t)cur * 16384u;

        if (c < NCH - 1) {
            const int nxt = cur ^ 1;
            STAGE_A((c + 1) * CHUNK, base + (uint32_t)nxt * 8192u);
            STAGE_B(c + 1, base + 16384u + (uint32_t)nxt * 16384u);
            CP_COMMIT();
        }

        const int nks = (c == NCH - 1) ? 1 : 4;
        #pragma unroll
        for (int ks = 0; ks < 4; ks++) {
            if (ks >= nks) break;
            const int kcol = ks * 32;
            uint32_t Af[2][4];
            #pragma unroll
            for (int mt = 0; mt < 2; mt++) {
                int r0 = rbase + ks * 16;
                int chunk = wm * 4 + mt * 2 + clane;   // px 8-block 0..7
                uint32_t ad = aA + (uint32_t)(r0 * 128 + ((chunk ^ (r0 & 7)) << 4));
                ldm_x4_trans(Af[mt], ad);
            }
            uint32_t Bf[2][4];
            #pragma unroll
            for (int p = 0; p < 2; p++) {
                int rowb = wn * 32 + p * 16 + browx4;
                int colb = kcol + bcolsel;
                uint32_t bd = aB + (uint32_t)(rowb * 128 + (colb ^ ((rowb & 7) * 16)));
                ldm_x4(Bf[p], bd);
            }
            #pragma unroll
            for (int p = 0; p < 2; p++)
                #pragma unroll
                for (int q = 0; q < 2; q++)
                    #pragma unroll
                    for (int mt = 0; mt < 2; mt++)
                        mma_fp16(acc[mt][p * 2 + q], Af[mt], &Bf[p][q * 2]);
        }
        CP_WAIT0();
        __syncthreads();
    }

    // epilogue: relu(D + b1) -> partial 1x1 conv, reduce in smem, atomicAdd gmem
    #pragma unroll
    for (int mt = 0; mt < 2; mt++) {
        #pragma unroll
        for (int half = 0; half < 2; half++) {
            float s0 = 0.f, s1 = 0.f;
            #pragma unroll
            for (int nt = 0; nt < 4; nt++) {
                int cl = wn * 32 + nt * 8 + tq * 2;
                float h0 = fmaxf(acc[mt][nt][half * 2 + 0] + s_b1[cl], 0.f);
                float h1 = fmaxf(acc[mt][nt][half * 2 + 1] + s_b1[cl + 1], 0.f);
                s0 += h0 * s_w2[cl] + h1 * s_w2[cl + 1];
                s1 += h0 * s_w2[128 + cl] + h1 * s_w2[128 + cl + 1];
            }
            s0 += __shfl_xor_sync(0xffffffffu, s0, 1);
            s0 += __shfl_xor_sync(0xffffffffu, s0, 2);
            s1 += __shfl_xor_sync(0xffffffffu, s1, 1);
            s1 += __shfl_xor_sync(0xffffffffu, s1, 2);
            if (tq == 0) {
                int px = wm * 32 + mt * 16 + half * 8 + gid;   // 0..63
                atomicAdd(&s_part[px * 2 + 0], s0);
                atomicAdd(&s_part[px * 2 + 1], s1);
            }
        }
    }
    __syncthreads();
    if (tid < 128) {
        int px = tid >> 1, o = tid & 1;
        atomicAdd(&outp[((n * 2 + o) * HH + y) * WW + ph * 64 + px],
                  s_part[px * 2 + o]);
    }
}

// ---------------- launch ----------------
extern "C" void kernel_launch(void* const* d_in, const int* in_sizes, int n_in,
                              void* d_out, int out_size) {
    const float* contour = (const float*)d_in[0];
    const float* feature = (const float*)d_in[1];
    const int*   batchi  = (const int*)d_in[2];
    const float* w1      = (const float*)d_in[3];
    const float* b1      = (const float*)d_in[4];
    const float* w2      = (const float*)d_in[5];
    const float* b2      = (const float*)d_in[6];
    float* out = (float*)d_out;
    float* out_scat = out + NIMG * 2 * HH * WW;

    static int attr_set = 0;
    if (!attr_set) {
        cudaFuncSetAttribute(k_conv_mma,
                             cudaFuncAttributeMaxDynamicSharedMemorySize,
                             DSMEM_BYTES);
        attr_set = 1;
    }

    k_prep1<<<NV * NC + 1, 128>>>(contour, batchi);
    k_prep2<<<FILL_BLOCKS + ZERO_BLOCKS + WS_BLOCKS + OINIT_BLOCKS, 256>>>(
        feature, w1, b2, out);
    k_scatter<<<dim3(HH / 8, NIMG), 128>>>(out_scat);
    k_conv_mma<<<4096, 256, DSMEM_BYTES>>>(b1, w2, out);
}